// round 11
// baseline (speedup 1.0000x reference)
#include <cuda_runtime.h>
#include <cuda_fp16.h>
#include <cstdint>
#include <mma.h>

using namespace nvcuda;

#define T_      8
#define H_      64
#define W_      64
#define C_      256
#define HEADS_  8
#define WS_     7
#define NPIX    (T_ * H_ * W_)          // 32768
#define M_      NPIX
#define N_      512
#define K_      256
#define NS_     (3 * WS_ * WS_)         // 147
#define SCALE_  0.17677669529663687f    // 32^-0.5

// projected q (pre-scaled) / k, fp16
__device__ __align__(16) __half g_qh[(size_t)NPIX * 256];
__device__ __align__(16) __half g_kh[(size_t)NPIX * 256];

__device__ __forceinline__ void cvt8(const float4 u, const float4 v, uint4& o)
{
    __half2 p0 = __floats2half2_rn(u.x, u.y);
    __half2 p1 = __floats2half2_rn(u.z, u.w);
    __half2 p2 = __floats2half2_rn(v.x, v.y);
    __half2 p3 = __floats2half2_rn(v.z, v.w);
    o.x = *(unsigned*)&p0; o.y = *(unsigned*)&p1;
    o.z = *(unsigned*)&p2; o.w = *(unsigned*)&p3;
}

// ---------------------------------------------------------------------------
// GEMM: A-resident (128 M-rows in smem, fp16); B register-double-buffered so
// the next chunk's global loads overlap the MMA section.
// ---------------------------------------------------------------------------
#define ALD 264                 // A pitch in halfs
#define BLD 40                  // B pitch in halfs
#define GSM_AS    0             // A: 128*264*2      = 67584 B
#define GSM_BS    67584         // B: 128*40*2       = 10240 B
#define GSM_WBUF  77824         // wbuf: 8*1088*4    = 34816 B
#define GSM_TOTAL 112640

__global__ void __launch_bounds__(256) gemm_qk_kernel(
    const float* __restrict__ x, const float* __restrict__ wqk)
{
    extern __shared__ __align__(16) char sm[];
    __half* As = (__half*)(sm + GSM_AS);
    __half* Bs = (__half*)(sm + GSM_BS);

    const int m0   = blockIdx.x * 128;
    const int tid  = threadIdx.x;
    const int wid  = tid >> 5;
    const int lane = tid & 31;
    const int wm   = wid & 3;
    const int wn   = wid >> 2;

    const int lr   = tid >> 1;
    const int lc16 = (tid & 1) * 16;

    // ---- stage full A tile (128 x 256) as fp16 ----
    #pragma unroll
    for (int c = 0; c < 8; c++) {
        const int col = c * 32 + lc16;
        const float* ap = x + (size_t)(m0 + lr) * K_ + col;
        uint4 o0, o1;
        cvt8(*(const float4*)(ap),     *(const float4*)(ap + 4),  o0);
        cvt8(*(const float4*)(ap + 8), *(const float4*)(ap + 12), o1);
        *(uint4*)(As + lr * ALD + col)     = o0;
        *(uint4*)(As + lr * ALD + col + 8) = o1;
    }

    for (int nc = 0; nc < 4; nc++) {
        const int n0 = nc * 128;

        wmma::fragment<wmma::accumulator, 16, 16, 16, float> acc[2][4];
        #pragma unroll
        for (int i = 0; i < 2; i++)
            #pragma unroll
            for (int j = 0; j < 4; j++)
                wmma::fill_fragment(acc[i][j], 0.0f);

        // preload first B chunk into registers
        uint4 rb0, rb1;
        {
            const float* bp = wqk + (size_t)(n0 + lr) * K_ + lc16;
            cvt8(*(const float4*)(bp),     *(const float4*)(bp + 4),  rb0);
            cvt8(*(const float4*)(bp + 8), *(const float4*)(bp + 12), rb1);
        }

        for (int kt = 0; kt < K_; kt += 32) {
            __syncthreads();            // previous Bs consumption done
            *(uint4*)(Bs + lr * BLD + lc16)     = rb0;
            *(uint4*)(Bs + lr * BLD + lc16 + 8) = rb1;
            // issue next chunk's loads (overlap with MMA below)
            if (kt + 32 < K_) {
                const float* bp = wqk + (size_t)(n0 + lr) * K_ + kt + 32 + lc16;
                cvt8(*(const float4*)(bp),     *(const float4*)(bp + 4),  rb0);
                cvt8(*(const float4*)(bp + 8), *(const float4*)(bp + 12), rb1);
            }
            __syncthreads();            // Bs ready

            #pragma unroll
            for (int kk = 0; kk < 32; kk += 16) {
                wmma::fragment<wmma::matrix_a, 16, 16, 16, __half, wmma::row_major> af0, af1;
                wmma::load_matrix_sync(af0, As + (wm * 32)      * ALD + kt + kk, ALD);
                wmma::load_matrix_sync(af1, As + (wm * 32 + 16) * ALD + kt + kk, ALD);
                #pragma unroll
                for (int j = 0; j < 4; j++) {
                    wmma::fragment<wmma::matrix_b, 16, 16, 16, __half, wmma::col_major> bf;
                    wmma::load_matrix_sync(bf, Bs + (wn * 64 + j * 16) * BLD + kk, BLD);
                    wmma::mma_sync(acc[0][j], af0, bf, acc[0][j]);
                    wmma::mma_sync(acc[1][j], af1, bf, acc[1][j]);
                }
            }
        }

        // epilogue for this N-chunk (wbuf region, warp-local)
        float* wbuf = (float*)(sm + GSM_WBUF) + wid * 1088;   // 16 rows x pitch 68
        const float sc = (n0 < 256) ? SCALE_ : 1.0f;
        const int row  = lane >> 1;
        const int colh = (lane & 1) * 32;

        #pragma unroll
        for (int i = 0; i < 2; i++) {
            #pragma unroll
            for (int j = 0; j < 4; j++)
                wmma::store_matrix_sync(wbuf + j * 16, acc[i][j], 68, wmma::mem_row_major);
            __syncwarp();

            const float* src = wbuf + row * 68 + colh;
            #pragma unroll
            for (int g = 0; g < 2; g++) {
                float4 u0 = *(const float4*)(src + g * 16);
                float4 u1 = *(const float4*)(src + g * 16 + 4);
                float4 u2 = *(const float4*)(src + g * 16 + 8);
                float4 u3 = *(const float4*)(src + g * 16 + 12);
                u0.x *= sc; u0.y *= sc; u0.z *= sc; u0.w *= sc;
                u1.x *= sc; u1.y *= sc; u1.z *= sc; u1.w *= sc;
                u2.x *= sc; u2.y *= sc; u2.z *= sc; u2.w *= sc;
                u3.x *= sc; u3.y *= sc; u3.z *= sc; u3.w *= sc;
                uint4 o0, o1;
                cvt8(u0, u1, o0);
                cvt8(u2, u3, o1);
                const int gr = m0 + wm * 32 + i * 16 + row;
                const int gc = n0 + wn * 64 + colh + g * 16;
                __half* dst = (n0 < 256) ? (g_qh + (size_t)gr * 256 + gc)
                                         : (g_kh + (size_t)gr * 256 + (gc - 256));
                *(uint4*)(dst)     = o0;
                *(uint4*)(dst + 8) = o1;
            }
            __syncwarp();
        }
    }
}

// ---------------------------------------------------------------------------
// Attention: one block per 2x2 pixel tile; each warp owns 2 pixels,
// keys strided by 4, unrolled x2 with 4 batched loads in flight.
// flows_k stores issued BEFORE the gather loop to interleave wavefronts.
// ---------------------------------------------------------------------------
__device__ __forceinline__ int reflect_idx(int idx, int L)
{
    const int period = 2 * (L - 1);
    int m = idx % period;
    if (m < 0) m += period;
    return (m > L - 1) ? (period - m) : m;
}

__global__ void __launch_bounds__(256) attn_kernel(
    const float* __restrict__ flows, float* __restrict__ out)
{
    const int bid = blockIdx.x;          // 8192 tiles
    const int t   = bid >> 10;
    const int th  = (bid >> 5) & 31;
    const int tw  = bid & 31;
    const int h0  = th * 2;
    const int w0  = tw * 2;

    __shared__ int   off_s[4][NS_ + 8];        // padded for unroll overrun
    __shared__ float fl_s[4][NS_ * 3];
    __shared__ float attn_s[4][HEADS_ * NS_];
    __shared__ int   s_fl[4][4];

    const int tid  = threadIdx.x;
    const int warp = tid >> 5;
    const int lane = tid & 31;

    if (tid < 16) {
        const int p   = tid >> 2;
        const int idx = tid & 3;
        const int hwp = (h0 + (p >> 1)) * 64 + w0 + (p & 1);
        const int p_  = idx >> 1, c_ = idx & 1;
        s_fl[p][idx] = (int)rintf(flows[(size_t)((t * 2 + p_) * 2 + c_) * 4096 + hwp]);
    }
    if (tid >= 224 && tid < 256) {             // zero the pad
        const int p = (tid - 224) >> 3;
        off_s[p][NS_ + ((tid - 224) & 7)] = 0;
    }
    __syncthreads();

    for (int e = tid; e < 4 * NS_; e += 256) {
        const int p  = e / NS_;
        const int s  = e - p * NS_;
        const int hp = h0 + (p >> 1);
        const int wp = w0 + (p & 1);
        const int slot = (s >= 49) + (s >= 98);
        const int r = s - slot * 49;
        const int a = r / 7;
        const int b = r - a * 7;
        int di = 0, dj = 0, tp = t;
        if (slot == 1) { tp = (t + 1 < T_) ? t + 1 : t - 2; di = s_fl[p][0]; dj = s_fl[p][1]; }
        if (slot == 2) { tp = (t - 1 >= 0) ? t - 1 : t + 2; di = s_fl[p][2]; dj = s_fl[p][3]; }
        const int li = reflect_idx(hp + di + a - 3, H_);
        const int lj = reflect_idx(wp + dj + b - 3, W_);
        off_s[p][s] = (tp << 12) + li * 64 + lj;
        fl_s[p][s * 3 + 0] = (float)(tp - t);
        fl_s[p][s * 3 + 1] = (float)(li - hp);
        fl_s[p][s * 3 + 2] = (float)(lj - wp);
    }
    __syncthreads();

    // ---- flows_k stores FIRST: interleave STG wavefronts with gather LDGs ----
    const size_t FBASE = (size_t)HEADS_ * T_ * 4096 * NS_;  // 38,535,168
    #pragma unroll
    for (int p = 0; p < 4; p++) {
        const int hwp = (h0 + (p >> 1)) * 64 + w0 + (p & 1);
        #pragma unroll
        for (int hd = 0; hd < HEADS_; hd++) {
            const size_t base = FBASE + (size_t)((hd * T_ + t) * 4096 + hwp) * (NS_ * 3);
            out[base + tid] = fl_s[p][tid];
            if (tid + 256 < NS_ * 3)
                out[base + tid + 256] = fl_s[p][tid + 256];
        }
    }

    // warps 0-3 -> pixels {0,1}, warps 4-7 -> pixels {2,3}; key stride 4
    const int p0    = (warp >> 2) * 2;
    const int p1    = p0 + 1;
    const int sbase = warp & 3;

    __half2 q[2][4];
    #pragma unroll
    for (int i = 0; i < 2; i++) {
        const int p = p0 + i;
        const int pixp = (t << 12) + (h0 + (p >> 1)) * 64 + w0 + (p & 1);
        const uint4 v = *(const uint4*)(g_qh + (size_t)pixp * 256 + lane * 8);
        q[i][0] = *(const __half2*)&v.x;
        q[i][1] = *(const __half2*)&v.y;
        q[i][2] = *(const __half2*)&v.z;
        q[i][3] = *(const __half2*)&v.w;
    }

    const __half* kb = g_kh + lane * 8;
    const int head = lane >> 2;
    const bool wr = (lane & 3) == 0;

    for (int s = sbase; s < NS_; s += 8) {
        const int sb  = (s + 4 < NS_) ? s + 4 : NS_;    // pad-safe
        const int o00 = off_s[p0][s],  o01 = off_s[p1][s];
        const int o10 = off_s[p0][sb], o11 = off_s[p1][sb];
        const uint4 k00 = *(const uint4*)(kb + ((size_t)o00 << 8));
        const uint4 k01 = *(const uint4*)(kb + ((size_t)o01 << 8));
        const uint4 k10 = *(const uint4*)(kb + ((size_t)o10 << 8));
        const uint4 k11 = *(const uint4*)(kb + ((size_t)o11 << 8));

        // pair A (key s)
        __half2 a0 = __hmul2(*(const __half2*)&k00.x, q[0][0]);
        __half2 a1 = __hmul2(*(const __half2*)&k01.x, q[1][0]);
        a0 = __hfma2(*(const __half2*)&k00.y, q[0][1], a0);
        a1 = __hfma2(*(const __half2*)&k01.y, q[1][1], a1);
        a0 = __hfma2(*(const __half2*)&k00.z, q[0][2], a0);
        a1 = __hfma2(*(const __half2*)&k01.z, q[1][2], a1);
        a0 = __hfma2(*(const __half2*)&k00.w, q[0][3], a0);
        a1 = __hfma2(*(const __half2*)&k01.w, q[1][3], a1);
        float v0 = __half2float(__hadd(__low2half(a0), __high2half(a0)));
        float v1 = __half2float(__hadd(__low2half(a1), __high2half(a1)));

        // pair B (key s+4)
        __half2 b0 = __hmul2(*(const __half2*)&k10.x, q[0][0]);
        __half2 b1 = __hmul2(*(const __half2*)&k11.x, q[1][0]);
        b0 = __hfma2(*(const __half2*)&k10.y, q[0][1], b0);
        b1 = __hfma2(*(const __half2*)&k11.y, q[1][1], b1);
        b0 = __hfma2(*(const __half2*)&k10.z, q[0][2], b0);
        b1 = __hfma2(*(const __half2*)&k11.z, q[1][2], b1);
        b0 = __hfma2(*(const __half2*)&k10.w, q[0][3], b0);
        b1 = __hfma2(*(const __half2*)&k11.w, q[1][3], b1);
        float v2 = __half2float(__hadd(__low2half(b0), __high2half(b0)));
        float v3 = __half2float(__hadd(__low2half(b1), __high2half(b1)));

        v0 += __shfl_xor_sync(0xffffffffu, v0, 1);
        v1 += __shfl_xor_sync(0xffffffffu, v1, 1);
        v2 += __shfl_xor_sync(0xffffffffu, v2, 1);
        v3 += __shfl_xor_sync(0xffffffffu, v3, 1);
        v0 += __shfl_xor_sync(0xffffffffu, v0, 2);
        v1 += __shfl_xor_sync(0xffffffffu, v1, 2);
        v2 += __shfl_xor_sync(0xffffffffu, v2, 2);
        v3 += __shfl_xor_sync(0xffffffffu, v3, 2);

        if (wr) {
            attn_s[p0][head * NS_ + s] = v0;
            attn_s[p1][head * NS_ + s] = v1;
            if (s + 4 < NS_) {
                attn_s[p0][head * NS_ + s + 4] = v2;
                attn_s[p1][head * NS_ + s + 4] = v3;
            }
        }
    }
    __syncthreads();

    // attn stores: (1, HEADS, T, H, W, 147)
    #pragma unroll
    for (int p = 0; p < 4; p++) {
        const int hwp = (h0 + (p >> 1)) * 64 + w0 + (p & 1);
        #pragma unroll
        for (int hd = 0; hd < HEADS_; hd++) {
            if (tid < NS_)
                out[(size_t)((hd * T_ + t) * 4096 + hwp) * NS_ + tid] =
                    attn_s[p][hd * NS_ + tid];
        }
    }
}

// ---------------------------------------------------------------------------
extern "C" void kernel_launch(void* const* d_in, const int* in_sizes, int n_in,
                              void* d_out, int out_size)
{
    const float* x     = (const float*)d_in[0];   // (8,64,64,256)
    const float* flows = (const float*)d_in[1];   // (1,8,2,2,64,64)
    const float* wqk   = (const float*)d_in[2];   // (512,256)
    float* out = (float*)d_out;

    cudaFuncSetAttribute(gemm_qk_kernel,
                         cudaFuncAttributeMaxDynamicSharedMemorySize, GSM_TOTAL);

    gemm_qk_kernel<<<M_ / 128, 256, GSM_TOTAL>>>(x, wqk);
    attn_kernel<<<NPIX / 4, 256>>>(flows, out);
}

// round 12
// speedup vs baseline: 1.3487x; 1.3487x over previous
#include <cuda_runtime.h>
#include <cuda_fp16.h>
#include <cstdint>
#include <mma.h>

using namespace nvcuda;

#define T_      8
#define H_      64
#define W_      64
#define C_      256
#define HEADS_  8
#define WS_     7
#define NPIX    (T_ * H_ * W_)          // 32768
#define M_      NPIX
#define N_      512
#define K_      256
#define NS_     (3 * WS_ * WS_)         // 147
#define SCALE_  0.17677669529663687f    // 32^-0.5

// projected q (pre-scaled) / k, fp16
__device__ __align__(16) __half g_qh[(size_t)NPIX * 256];
__device__ __align__(16) __half g_kh[(size_t)NPIX * 256];

__device__ __forceinline__ void cvt8(const float4 u, const float4 v, uint4& o)
{
    __half2 p0 = __floats2half2_rn(u.x, u.y);
    __half2 p1 = __floats2half2_rn(u.z, u.w);
    __half2 p2 = __floats2half2_rn(v.x, v.y);
    __half2 p3 = __floats2half2_rn(v.z, v.w);
    o.x = *(unsigned*)&p0; o.y = *(unsigned*)&p1;
    o.z = *(unsigned*)&p2; o.w = *(unsigned*)&p3;
}

// ---------------------------------------------------------------------------
// GEMM: A-resident (128 M-rows fp16 in smem). wbuf ALIASES Bs (epilogue runs
// only when Bs is dead) -> 100 KB smem -> 2 blocks/SM.
// ---------------------------------------------------------------------------
#define ALD 264                 // A pitch in halfs
#define BLD 40                  // B pitch in halfs
#define GSM_AS    0             // A: 128*264*2 = 67584 B
#define GSM_BS    67584         // B: 128*40*2  = 10240 B   (aliased by wbuf)
#define GSM_WBUF  67584         // wbuf: 8*1088*4 = 34816 B
#define GSM_TOTAL 102400

__global__ void __launch_bounds__(256) gemm_qk_kernel(
    const float* __restrict__ x, const float* __restrict__ wqk)
{
    extern __shared__ __align__(16) char sm[];
    __half* As = (__half*)(sm + GSM_AS);
    __half* Bs = (__half*)(sm + GSM_BS);

    const int m0   = blockIdx.x * 128;
    const int tid  = threadIdx.x;
    const int wid  = tid >> 5;
    const int lane = tid & 31;
    const int wm   = wid & 3;    // 4 M-groups of 32 rows
    const int wn   = wid >> 2;   // 2 N-groups of 64 cols

    const int lr   = tid >> 1;          // 0..127
    const int lc16 = (tid & 1) * 16;    // 0 or 16

    // ---- stage full A tile (128 x 256) as fp16 ----
    #pragma unroll
    for (int c = 0; c < 8; c++) {
        const int col = c * 32 + lc16;
        const float* ap = x + (size_t)(m0 + lr) * K_ + col;
        uint4 o0, o1;
        cvt8(*(const float4*)(ap),     *(const float4*)(ap + 4),  o0);
        cvt8(*(const float4*)(ap + 8), *(const float4*)(ap + 12), o1);
        *(uint4*)(As + lr * ALD + col)     = o0;
        *(uint4*)(As + lr * ALD + col + 8) = o1;
    }

    for (int nc = 0; nc < 4; nc++) {
        const int n0 = nc * 128;

        wmma::fragment<wmma::accumulator, 16, 16, 16, float> acc[2][4];
        #pragma unroll
        for (int i = 0; i < 2; i++)
            #pragma unroll
            for (int j = 0; j < 4; j++)
                wmma::fill_fragment(acc[i][j], 0.0f);

        for (int kt = 0; kt < K_; kt += 32) {
            const float* bp = wqk + (size_t)(n0 + lr) * K_ + kt + lc16;
            uint4 ob0, ob1;
            cvt8(*(const float4*)(bp),     *(const float4*)(bp + 4),  ob0);
            cvt8(*(const float4*)(bp + 8), *(const float4*)(bp + 12), ob1);
            __syncthreads();   // prev Bs consumption / prev epilogue wbuf done
            *(uint4*)(Bs + lr * BLD + lc16)     = ob0;
            *(uint4*)(Bs + lr * BLD + lc16 + 8) = ob1;
            __syncthreads();   // Bs ready

            #pragma unroll
            for (int kk = 0; kk < 32; kk += 16) {
                wmma::fragment<wmma::matrix_a, 16, 16, 16, __half, wmma::row_major> af0, af1;
                wmma::load_matrix_sync(af0, As + (wm * 32)      * ALD + kt + kk, ALD);
                wmma::load_matrix_sync(af1, As + (wm * 32 + 16) * ALD + kt + kk, ALD);
                #pragma unroll
                for (int j = 0; j < 4; j++) {
                    wmma::fragment<wmma::matrix_b, 16, 16, 16, __half, wmma::col_major> bf;
                    wmma::load_matrix_sync(bf, Bs + (wn * 64 + j * 16) * BLD + kk, BLD);
                    wmma::mma_sync(acc[0][j], af0, bf, acc[0][j]);
                    wmma::mma_sync(acc[1][j], af1, bf, acc[1][j]);
                }
            }
        }
        __syncthreads();   // all warps done reading Bs -> wbuf may clobber it

        // epilogue for this N-chunk (wbuf aliases Bs)
        float* wbuf = (float*)(sm + GSM_WBUF) + wid * 1088;   // 16 rows x pitch 68
        const float sc = (n0 < 256) ? SCALE_ : 1.0f;
        const int row  = lane >> 1;
        const int colh = (lane & 1) * 32;

        #pragma unroll
        for (int i = 0; i < 2; i++) {
            #pragma unroll
            for (int j = 0; j < 4; j++)
                wmma::store_matrix_sync(wbuf + j * 16, acc[i][j], 68, wmma::mem_row_major);
            __syncwarp();

            const float* src = wbuf + row * 68 + colh;
            #pragma unroll
            for (int g = 0; g < 2; g++) {
                float4 u0 = *(const float4*)(src + g * 16);
                float4 u1 = *(const float4*)(src + g * 16 + 4);
                float4 u2 = *(const float4*)(src + g * 16 + 8);
                float4 u3 = *(const float4*)(src + g * 16 + 12);
                u0.x *= sc; u0.y *= sc; u0.z *= sc; u0.w *= sc;
                u1.x *= sc; u1.y *= sc; u1.z *= sc; u1.w *= sc;
                u2.x *= sc; u2.y *= sc; u2.z *= sc; u2.w *= sc;
                u3.x *= sc; u3.y *= sc; u3.z *= sc; u3.w *= sc;
                uint4 o0, o1;
                cvt8(u0, u1, o0);
                cvt8(u2, u3, o1);
                const int gr = m0 + wm * 32 + i * 16 + row;
                const int gc = n0 + wn * 64 + colh + g * 16;
                __half* dst = (n0 < 256) ? (g_qh + (size_t)gr * 256 + gc)
                                         : (g_kh + (size_t)gr * 256 + (gc - 256));
                *(uint4*)(dst)     = o0;
                *(uint4*)(dst + 8) = o1;
            }
            __syncwarp();
        }
    }
}

// ---------------------------------------------------------------------------
// Attention (round-9 proven version): one block per 2x2 pixel tile;
// each warp owns 2 pixels, keys strided by 4; single prefetch pipeline.
// __launch_bounds__(256, 6) caps regs for 6 blocks/SM.
// ---------------------------------------------------------------------------
__device__ __forceinline__ int reflect_idx(int idx, int L)
{
    const int period = 2 * (L - 1);
    int m = idx % period;
    if (m < 0) m += period;
    return (m > L - 1) ? (period - m) : m;
}

__global__ void __launch_bounds__(256, 6) attn_kernel(
    const float* __restrict__ flows, float* __restrict__ out)
{
    const int bid = blockIdx.x;          // 8192 tiles
    const int t   = bid >> 10;
    const int th  = (bid >> 5) & 31;
    const int tw  = bid & 31;
    const int h0  = th * 2;
    const int w0  = tw * 2;

    __shared__ int   off_s[4][NS_ + 8];        // padded for prefetch-overrun
    __shared__ float fl_s[4][NS_ * 3];
    __shared__ float attn_s[4][HEADS_ * NS_];
    __shared__ int   s_fl[4][4];

    const int tid  = threadIdx.x;
    const int warp = tid >> 5;
    const int lane = tid & 31;

    if (tid < 16) {
        const int p   = tid >> 2;
        const int idx = tid & 3;
        const int hwp = (h0 + (p >> 1)) * 64 + w0 + (p & 1);
        const int p_  = idx >> 1, c_ = idx & 1;
        s_fl[p][idx] = (int)rintf(flows[(size_t)((t * 2 + p_) * 2 + c_) * 4096 + hwp]);
    }
    if (tid >= 224 && tid < 256) {             // zero the prefetch pad
        const int p = (tid - 224) >> 3;
        off_s[p][NS_ + ((tid - 224) & 7)] = 0;
    }
    __syncthreads();

    for (int e = tid; e < 4 * NS_; e += 256) {
        const int p  = e / NS_;
        const int s  = e - p * NS_;
        const int hp = h0 + (p >> 1);
        const int wp = w0 + (p & 1);
        const int slot = (s >= 49) + (s >= 98);
        const int r = s - slot * 49;
        const int a = r / 7;
        const int b = r - a * 7;
        int di = 0, dj = 0, tp = t;
        if (slot == 1) { tp = (t + 1 < T_) ? t + 1 : t - 2; di = s_fl[p][0]; dj = s_fl[p][1]; }
        if (slot == 2) { tp = (t - 1 >= 0) ? t - 1 : t + 2; di = s_fl[p][2]; dj = s_fl[p][3]; }
        const int li = reflect_idx(hp + di + a - 3, H_);
        const int lj = reflect_idx(wp + dj + b - 3, W_);
        off_s[p][s] = (tp << 12) + li * 64 + lj;
        fl_s[p][s * 3 + 0] = (float)(tp - t);
        fl_s[p][s * 3 + 1] = (float)(li - hp);
        fl_s[p][s * 3 + 2] = (float)(lj - wp);
    }
    __syncthreads();

    // warps 0-3 -> pixels {0,1}, warps 4-7 -> pixels {2,3}; key stride 4
    const int p0    = (warp >> 2) * 2;
    const int sbase = warp & 3;

    __half2 q[2][4];
    #pragma unroll
    for (int i = 0; i < 2; i++) {
        const int p = p0 + i;
        const int pixp = (t << 12) + (h0 + (p >> 1)) * 64 + w0 + (p & 1);
        const uint4 v = *(const uint4*)(g_qh + (size_t)pixp * 256 + lane * 8);
        q[i][0] = *(const __half2*)&v.x;
        q[i][1] = *(const __half2*)&v.y;
        q[i][2] = *(const __half2*)&v.z;
        q[i][3] = *(const __half2*)&v.w;
    }

    const __half* kb = g_kh + lane * 8;
    const int head = lane >> 2;
    const bool wr = (lane & 3) == 0;

    uint4 kv[2];
    kv[0] = *(const uint4*)(kb + ((size_t)off_s[p0][sbase]     << 8));
    kv[1] = *(const uint4*)(kb + ((size_t)off_s[p0 + 1][sbase] << 8));

    for (int s = sbase; s < NS_; s += 4) {
        const int sn = (s + 4 < NS_) ? s + 4 : NS_;
        uint4 nv0 = *(const uint4*)(kb + ((size_t)off_s[p0][sn]     << 8));
        uint4 nv1 = *(const uint4*)(kb + ((size_t)off_s[p0 + 1][sn] << 8));

        __half2 a0 = __hmul2(*(const __half2*)&kv[0].x, q[0][0]);
        __half2 a1 = __hmul2(*(const __half2*)&kv[1].x, q[1][0]);
        a0 = __hfma2(*(const __half2*)&kv[0].y, q[0][1], a0);
        a1 = __hfma2(*(const __half2*)&kv[1].y, q[1][1], a1);
        a0 = __hfma2(*(const __half2*)&kv[0].z, q[0][2], a0);
        a1 = __hfma2(*(const __half2*)&kv[1].z, q[1][2], a1);
        a0 = __hfma2(*(const __half2*)&kv[0].w, q[0][3], a0);
        a1 = __hfma2(*(const __half2*)&kv[1].w, q[1][3], a1);
        float v0 = __half2float(__hadd(__low2half(a0), __high2half(a0)));
        float v1 = __half2float(__hadd(__low2half(a1), __high2half(a1)));
        v0 += __shfl_xor_sync(0xffffffffu, v0, 1);
        v1 += __shfl_xor_sync(0xffffffffu, v1, 1);
        v0 += __shfl_xor_sync(0xffffffffu, v0, 2);
        v1 += __shfl_xor_sync(0xffffffffu, v1, 2);
        if (wr) {
            attn_s[p0][head * NS_ + s]     = v0;
            attn_s[p0 + 1][head * NS_ + s] = v1;
        }
        kv[0] = nv0;
        kv[1] = nv1;
    }
    __syncthreads();

    // attn stores: (1, HEADS, T, H, W, 147)
    #pragma unroll
    for (int p = 0; p < 4; p++) {
        const int hwp = (h0 + (p >> 1)) * 64 + w0 + (p & 1);
        #pragma unroll
        for (int hd = 0; hd < HEADS_; hd++) {
            if (tid < NS_)
                out[(size_t)((hd * T_ + t) * 4096 + hwp) * NS_ + tid] =
                    attn_s[p][hd * NS_ + tid];
        }
    }

    // flows_k stores: (1, HEADS, T, H, W, 147, 3)
    const size_t FBASE = (size_t)HEADS_ * T_ * 4096 * NS_;  // 38,535,168
    #pragma unroll
    for (int p = 0; p < 4; p++) {
        const int hwp = (h0 + (p >> 1)) * 64 + w0 + (p & 1);
        #pragma unroll
        for (int hd = 0; hd < HEADS_; hd++) {
            const size_t base = FBASE + (size_t)((hd * T_ + t) * 4096 + hwp) * (NS_ * 3);
            out[base + tid] = fl_s[p][tid];
            if (tid + 256 < NS_ * 3)
                out[base + tid + 256] = fl_s[p][tid + 256];
        }
    }
}

// ---------------------------------------------------------------------------
extern "C" void kernel_launch(void* const* d_in, const int* in_sizes, int n_in,
                              void* d_out, int out_size)
{
    const float* x     = (const float*)d_in[0];   // (8,64,64,256)
    const float* flows = (const float*)d_in[1];   // (1,8,2,2,64,64)
    const float* wqk   = (const float*)d_in[2];   // (512,256)
    float* out = (float*)d_out;

    cudaFuncSetAttribute(gemm_qk_kernel,
                         cudaFuncAttributeMaxDynamicSharedMemorySize, GSM_TOTAL);

    gemm_qk_kernel<<<M_ / 128, 256, GSM_TOTAL>>>(x, wqk);
    attn_kernel<<<NPIX / 4, 256>>>(flows, out);
}

// round 13
// speedup vs baseline: 1.4436x; 1.0703x over previous
#include <cuda_runtime.h>
#include <cuda_fp16.h>
#include <cstdint>
#include <mma.h>

using namespace nvcuda;

#define T_      8
#define H_      64
#define W_      64
#define C_      256
#define HEADS_  8
#define WS_     7
#define NPIX    (T_ * H_ * W_)          // 32768
#define M_      NPIX
#define N_      512
#define K_      256
#define NS_     (3 * WS_ * WS_)         // 147
#define SCALE_  0.17677669529663687f    // 32^-0.5

// projected q (pre-scaled) / k, fp16
__device__ __align__(16) __half g_qh[(size_t)NPIX * 256];
__device__ __align__(16) __half g_kh[(size_t)NPIX * 256];

__device__ __forceinline__ void cvt8(const float4 u, const float4 v, uint4& o)
{
    __half2 p0 = __floats2half2_rn(u.x, u.y);
    __half2 p1 = __floats2half2_rn(u.z, u.w);
    __half2 p2 = __floats2half2_rn(v.x, v.y);
    __half2 p3 = __floats2half2_rn(v.z, v.w);
    o.x = *(unsigned*)&p0; o.y = *(unsigned*)&p1;
    o.z = *(unsigned*)&p2; o.w = *(unsigned*)&p3;
}

// ---------------------------------------------------------------------------
// GEMM: A-resident (128 M-rows fp16 in smem) + FULL 128x256 B chunk staged
// per N-step. 3 syncthreads per N-chunk; MMA runs 16 k-steps uninterrupted.
// wbuf aliases Bs (dead during epilogue).
// ---------------------------------------------------------------------------
#define ALD 264                 // pitch in halfs (A and B)
#define GSM_AS    0             // A: 128*264*2 = 67584 B
#define GSM_BS    67584         // B: 128*264*2 = 67584 B (aliased by wbuf)
#define GSM_WBUF  67584
#define GSM_TOTAL 135168

__global__ void __launch_bounds__(256) gemm_qk_kernel(
    const float* __restrict__ x, const float* __restrict__ wqk)
{
    extern __shared__ __align__(16) char sm[];
    __half* As = (__half*)(sm + GSM_AS);
    __half* Bs = (__half*)(sm + GSM_BS);

    const int m0   = blockIdx.x * 128;
    const int tid  = threadIdx.x;
    const int wid  = tid >> 5;
    const int lane = tid & 31;
    const int wm   = wid & 3;    // 4 M-groups of 32 rows
    const int wn   = wid >> 2;   // 2 N-groups of 64 cols

    const int lr   = tid >> 1;          // 0..127
    const int lc16 = (tid & 1) * 16;    // 0 or 16

    // ---- stage full A tile (128 x 256) as fp16, massive MLP ----
    #pragma unroll
    for (int c = 0; c < 8; c++) {
        const int col = c * 32 + lc16;
        const float* ap = x + (size_t)(m0 + lr) * K_ + col;
        uint4 o0, o1;
        cvt8(*(const float4*)(ap),     *(const float4*)(ap + 4),  o0);
        cvt8(*(const float4*)(ap + 8), *(const float4*)(ap + 12), o1);
        *(uint4*)(As + lr * ALD + col)     = o0;
        *(uint4*)(As + lr * ALD + col + 8) = o1;
    }

    for (int nc = 0; nc < 4; nc++) {
        const int n0 = nc * 128;

        __syncthreads();   // prev epilogue (wbuf=Bs) done; A ready on first pass

        // ---- stage full B chunk (128 N-rows x 256 K) as fp16 ----
        #pragma unroll
        for (int c = 0; c < 8; c++) {
            const int col = c * 32 + lc16;
            const float* bp = wqk + (size_t)(n0 + lr) * K_ + col;
            uint4 o0, o1;
            cvt8(*(const float4*)(bp),     *(const float4*)(bp + 4),  o0);
            cvt8(*(const float4*)(bp + 8), *(const float4*)(bp + 12), o1);
            *(uint4*)(Bs + lr * ALD + col)     = o0;
            *(uint4*)(Bs + lr * ALD + col + 8) = o1;
        }
        __syncthreads();   // B ready

        wmma::fragment<wmma::accumulator, 16, 16, 16, float> acc[2][4];
        #pragma unroll
        for (int i = 0; i < 2; i++)
            #pragma unroll
            for (int j = 0; j < 4; j++)
                wmma::fill_fragment(acc[i][j], 0.0f);

        // ---- 16 uninterrupted k-steps ----
        #pragma unroll 4
        for (int kt = 0; kt < K_; kt += 16) {
            wmma::fragment<wmma::matrix_a, 16, 16, 16, __half, wmma::row_major> af0, af1;
            wmma::load_matrix_sync(af0, As + (wm * 32)      * ALD + kt, ALD);
            wmma::load_matrix_sync(af1, As + (wm * 32 + 16) * ALD + kt, ALD);
            #pragma unroll
            for (int j = 0; j < 4; j++) {
                wmma::fragment<wmma::matrix_b, 16, 16, 16, __half, wmma::col_major> bf;
                wmma::load_matrix_sync(bf, Bs + (wn * 64 + j * 16) * ALD + kt, ALD);
                wmma::mma_sync(acc[0][j], af0, bf, acc[0][j]);
                wmma::mma_sync(acc[1][j], af1, bf, acc[1][j]);
            }
        }
        __syncthreads();   // all warps done reading Bs -> wbuf may clobber it

        // ---- epilogue (wbuf aliases Bs) ----
        float* wbuf = (float*)(sm + GSM_WBUF) + wid * 1088;   // 16 rows x pitch 68
        const float sc = (n0 < 256) ? SCALE_ : 1.0f;
        const int row  = lane >> 1;
        const int colh = (lane & 1) * 32;

        #pragma unroll
        for (int i = 0; i < 2; i++) {
            #pragma unroll
            for (int j = 0; j < 4; j++)
                wmma::store_matrix_sync(wbuf + j * 16, acc[i][j], 68, wmma::mem_row_major);
            __syncwarp();

            const float* src = wbuf + row * 68 + colh;
            #pragma unroll
            for (int g = 0; g < 2; g++) {
                float4 u0 = *(const float4*)(src + g * 16);
                float4 u1 = *(const float4*)(src + g * 16 + 4);
                float4 u2 = *(const float4*)(src + g * 16 + 8);
                float4 u3 = *(const float4*)(src + g * 16 + 12);
                u0.x *= sc; u0.y *= sc; u0.z *= sc; u0.w *= sc;
                u1.x *= sc; u1.y *= sc; u1.z *= sc; u1.w *= sc;
                u2.x *= sc; u2.y *= sc; u2.z *= sc; u2.w *= sc;
                u3.x *= sc; u3.y *= sc; u3.z *= sc; u3.w *= sc;
                uint4 o0, o1;
                cvt8(u0, u1, o0);
                cvt8(u2, u3, o1);
                const int gr = m0 + wm * 32 + i * 16 + row;
                const int gc = n0 + wn * 64 + colh + g * 16;
                __half* dst = (n0 < 256) ? (g_qh + (size_t)gr * 256 + gc)
                                         : (g_kh + (size_t)gr * 256 + (gc - 256));
                *(uint4*)(dst)     = o0;
                *(uint4*)(dst + 8) = o1;
            }
            __syncwarp();
        }
    }
}

// ---------------------------------------------------------------------------
// Attention (exact round-10 best: 212.7us): one block per 2x2 pixel tile;
// each warp owns 2 pixels, keys strided by 4; single prefetch pipeline.
// NO launch_bounds cap (reg cap caused l1tex re-load traffic in R12).
// ---------------------------------------------------------------------------
__device__ __forceinline__ int reflect_idx(int idx, int L)
{
    const int period = 2 * (L - 1);
    int m = idx % period;
    if (m < 0) m += period;
    return (m > L - 1) ? (period - m) : m;
}

__global__ void __launch_bounds__(256) attn_kernel(
    const float* __restrict__ flows, float* __restrict__ out)
{
    const int bid = blockIdx.x;          // 8192 tiles
    const int t   = bid >> 10;
    const int th  = (bid >> 5) & 31;
    const int tw  = bid & 31;
    const int h0  = th * 2;
    const int w0  = tw * 2;

    __shared__ int   off_s[4][NS_ + 8];        // padded for prefetch-overrun
    __shared__ float fl_s[4][NS_ * 3];
    __shared__ float attn_s[4][HEADS_ * NS_];
    __shared__ int   s_fl[4][4];

    const int tid  = threadIdx.x;
    const int warp = tid >> 5;
    const int lane = tid & 31;

    if (tid < 16) {
        const int p   = tid >> 2;
        const int idx = tid & 3;
        const int hwp = (h0 + (p >> 1)) * 64 + w0 + (p & 1);
        const int p_  = idx >> 1, c_ = idx & 1;
        s_fl[p][idx] = (int)rintf(flows[(size_t)((t * 2 + p_) * 2 + c_) * 4096 + hwp]);
    }
    if (tid >= 224 && tid < 256) {             // zero the prefetch pad
        const int p = (tid - 224) >> 3;
        off_s[p][NS_ + ((tid - 224) & 7)] = 0;
    }
    __syncthreads();

    for (int e = tid; e < 4 * NS_; e += 256) {
        const int p  = e / NS_;
        const int s  = e - p * NS_;
        const int hp = h0 + (p >> 1);
        const int wp = w0 + (p & 1);
        const int slot = (s >= 49) + (s >= 98);
        const int r = s - slot * 49;
        const int a = r / 7;
        const int b = r - a * 7;
        int di = 0, dj = 0, tp = t;
        if (slot == 1) { tp = (t + 1 < T_) ? t + 1 : t - 2; di = s_fl[p][0]; dj = s_fl[p][1]; }
        if (slot == 2) { tp = (t - 1 >= 0) ? t - 1 : t + 2; di = s_fl[p][2]; dj = s_fl[p][3]; }
        const int li = reflect_idx(hp + di + a - 3, H_);
        const int lj = reflect_idx(wp + dj + b - 3, W_);
        off_s[p][s] = (tp << 12) + li * 64 + lj;
        fl_s[p][s * 3 + 0] = (float)(tp - t);
        fl_s[p][s * 3 + 1] = (float)(li - hp);
        fl_s[p][s * 3 + 2] = (float)(lj - wp);
    }
    __syncthreads();

    // warps 0-3 -> pixels {0,1}, warps 4-7 -> pixels {2,3}; key stride 4
    const int p0    = (warp >> 2) * 2;
    const int sbase = warp & 3;

    __half2 q[2][4];
    #pragma unroll
    for (int i = 0; i < 2; i++) {
        const int p = p0 + i;
        const int pixp = (t << 12) + (h0 + (p >> 1)) * 64 + w0 + (p & 1);
        const uint4 v = *(const uint4*)(g_qh + (size_t)pixp * 256 + lane * 8);
        q[i][0] = *(const __half2*)&v.x;
        q[i][1] = *(const __half2*)&v.y;
        q[i][2] = *(const __half2*)&v.z;
        q[i][3] = *(const __half2*)&v.w;
    }

    const __half* kb = g_kh + lane * 8;
    const int head = lane >> 2;
    const bool wr = (lane & 3) == 0;

    uint4 kv[2];
    kv[0] = *(const uint4*)(kb + ((size_t)off_s[p0][sbase]     << 8));
    kv[1] = *(const uint4*)(kb + ((size_t)off_s[p0 + 1][sbase] << 8));

    for (int s = sbase; s < NS_; s += 4) {
        const int sn = (s + 4 < NS_) ? s + 4 : NS_;
        uint4 nv0 = *(const uint4*)(kb + ((size_t)off_s[p0][sn]     << 8));
        uint4 nv1 = *(const uint4*)(kb + ((size_t)off_s[p0 + 1][sn] << 8));

        __half2 a0 = __hmul2(*(const __half2*)&kv[0].x, q[0][0]);
        __half2 a1 = __hmul2(*(const __half2*)&kv[1].x, q[1][0]);
        a0 = __hfma2(*(const __half2*)&kv[0].y, q[0][1], a0);
        a1 = __hfma2(*(const __half2*)&kv[1].y, q[1][1], a1);
        a0 = __hfma2(*(const __half2*)&kv[0].z, q[0][2], a0);
        a1 = __hfma2(*(const __half2*)&kv[1].z, q[1][2], a1);
        a0 = __hfma2(*(const __half2*)&kv[0].w, q[0][3], a0);
        a1 = __hfma2(*(const __half2*)&kv[1].w, q[1][3], a1);
        float v0 = __half2float(__hadd(__low2half(a0), __high2half(a0)));
        float v1 = __half2float(__hadd(__low2half(a1), __high2half(a1)));
        v0 += __shfl_xor_sync(0xffffffffu, v0, 1);
        v1 += __shfl_xor_sync(0xffffffffu, v1, 1);
        v0 += __shfl_xor_sync(0xffffffffu, v0, 2);
        v1 += __shfl_xor_sync(0xffffffffu, v1, 2);
        if (wr) {
            attn_s[p0][head * NS_ + s]     = v0;
            attn_s[p0 + 1][head * NS_ + s] = v1;
        }
        kv[0] = nv0;
        kv[1] = nv1;
    }
    __syncthreads();

    // attn stores: (1, HEADS, T, H, W, 147)
    #pragma unroll
    for (int p = 0; p < 4; p++) {
        const int hwp = (h0 + (p >> 1)) * 64 + w0 + (p & 1);
        #pragma unroll
        for (int hd = 0; hd < HEADS_; hd++) {
            if (tid < NS_)
                out[(size_t)((hd * T_ + t) * 4096 + hwp) * NS_ + tid] =
                    attn_s[p][hd * NS_ + tid];
        }
    }

    // flows_k stores: (1, HEADS, T, H, W, 147, 3)
    const size_t FBASE = (size_t)HEADS_ * T_ * 4096 * NS_;  // 38,535,168
    #pragma unroll
    for (int p = 0; p < 4; p++) {
        const int hwp = (h0 + (p >> 1)) * 64 + w0 + (p & 1);
        #pragma unroll
        for (int hd = 0; hd < HEADS_; hd++) {
            const size_t base = FBASE + (size_t)((hd * T_ + t) * 4096 + hwp) * (NS_ * 3);
            out[base + tid] = fl_s[p][tid];
            if (tid + 256 < NS_ * 3)
                out[base + tid + 256] = fl_s[p][tid + 256];
        }
    }
}

// ---------------------------------------------------------------------------
extern "C" void kernel_launch(void* const* d_in, const int* in_sizes, int n_in,
                              void* d_out, int out_size)
{
    const float* x     = (const float*)d_in[0];   // (8,64,64,256)
    const float* flows = (const float*)d_in[1];   // (1,8,2,2,64,64)
    const float* wqk   = (const float*)d_in[2];   // (512,256)
    float* out = (float*)d_out;

    cudaFuncSetAttribute(gemm_qk_kernel,
                         cudaFuncAttributeMaxDynamicSharedMemorySize, GSM_TOTAL);

    gemm_qk_kernel<<<M_ / 128, 256, GSM_TOTAL>>>(x, wqk);
    attn_kernel<<<NPIX / 4, 256>>>(flows, out);
}

// round 15
// speedup vs baseline: 1.5220x; 1.0544x over previous
#include <cuda_runtime.h>
#include <cuda_fp16.h>
#include <cstdint>
#include <mma.h>

using namespace nvcuda;

#define T_      8
#define H_      64
#define W_      64
#define C_      256
#define HEADS_  8
#define WS_     7
#define NPIX    (T_ * H_ * W_)          // 32768
#define M_      NPIX
#define N_      512
#define K_      256
#define NS_     (3 * WS_ * WS_)         // 147
#define SCALE_  0.17677669529663687f    // 32^-0.5

// projected q (pre-scaled) / k, fp16; W_qk pre-converted to fp16
__device__ __align__(16) __half g_qh[(size_t)NPIX * 256];
__device__ __align__(16) __half g_kh[(size_t)NPIX * 256];
__device__ __align__(16) __half g_wh[(size_t)512 * 256];

__device__ __forceinline__ void cvt8(const float4 u, const float4 v, uint4& o)
{
    __half2 p0 = __floats2half2_rn(u.x, u.y);
    __half2 p1 = __floats2half2_rn(u.z, u.w);
    __half2 p2 = __floats2half2_rn(v.x, v.y);
    __half2 p3 = __floats2half2_rn(v.z, v.w);
    o.x = *(unsigned*)&p0; o.y = *(unsigned*)&p1;
    o.z = *(unsigned*)&p2; o.w = *(unsigned*)&p3;
}

// ---------------------------------------------------------------------------
// W_qk fp32 -> fp16 (131072 elems)
// ---------------------------------------------------------------------------
__global__ void __launch_bounds__(256) cvtw_kernel(const float* __restrict__ wqk)
{
    const int idx = blockIdx.x * 256 + threadIdx.x;    // 16384 threads
    const float* src = wqk + (size_t)idx * 8;
    uint4 o;
    cvt8(*(const float4*)src, *(const float4*)(src + 4), o);
    *(uint4*)(g_wh + (size_t)idx * 8) = o;
}

// ---------------------------------------------------------------------------
// GEMM: A-resident (128 M-rows fp16 in smem) + full 128x256 B chunk staged
// per N-step from fp16 g_wh. wbuf aliases Bs.
// ---------------------------------------------------------------------------
#define ALD 264
#define GSM_AS    0             // A: 128*264*2 = 67584 B
#define GSM_BS    67584         // B: 128*264*2 = 67584 B (aliased by wbuf)
#define GSM_WBUF  67584
#define GSM_TOTAL 135168

__global__ void __launch_bounds__(256) gemm_qk_kernel(const float* __restrict__ x)
{
    extern __shared__ __align__(16) char sm[];
    __half* As = (__half*)(sm + GSM_AS);
    __half* Bs = (__half*)(sm + GSM_BS);

    const int m0   = blockIdx.x * 128;
    const int tid  = threadIdx.x;
    const int wid  = tid >> 5;
    const int lane = tid & 31;
    const int wm   = wid & 3;
    const int wn   = wid >> 2;

    const int lr   = tid >> 1;          // 0..127
    const int lc16 = (tid & 1) * 16;    // 0 or 16

    // stage full A tile (128 x 256) as fp16
    #pragma unroll
    for (int c = 0; c < 8; c++) {
        const int col = c * 32 + lc16;
        const float* ap = x + (size_t)(m0 + lr) * K_ + col;
        uint4 o0, o1;
        cvt8(*(const float4*)(ap),     *(const float4*)(ap + 4),  o0);
        cvt8(*(const float4*)(ap + 8), *(const float4*)(ap + 12), o1);
        *(uint4*)(As + lr * ALD + col)     = o0;
        *(uint4*)(As + lr * ALD + col + 8) = o1;
    }

    for (int nc = 0; nc < 4; nc++) {
        const int n0 = nc * 128;

        __syncthreads();   // prev epilogue done; A ready on first pass

        // stage full B chunk (128 x 256 halfs) from fp16 source — 16 halfs/step
        #pragma unroll
        for (int c = 0; c < 8; c++) {
            const int col = c * 32 + lc16;
            const __half* bp = g_wh + (size_t)(n0 + lr) * 256 + col;
            const uint4 o0 = *(const uint4*)(bp);
            const uint4 o1 = *(const uint4*)(bp + 8);
            *(uint4*)(Bs + lr * ALD + col)     = o0;
            *(uint4*)(Bs + lr * ALD + col + 8) = o1;
        }
        __syncthreads();   // B ready

        wmma::fragment<wmma::accumulator, 16, 16, 16, float> acc[2][4];
        #pragma unroll
        for (int i = 0; i < 2; i++)
            #pragma unroll
            for (int j = 0; j < 4; j++)
                wmma::fill_fragment(acc[i][j], 0.0f);

        #pragma unroll 4
        for (int kt = 0; kt < K_; kt += 16) {
            wmma::fragment<wmma::matrix_a, 16, 16, 16, __half, wmma::row_major> af0, af1;
            wmma::load_matrix_sync(af0, As + (wm * 32)      * ALD + kt, ALD);
            wmma::load_matrix_sync(af1, As + (wm * 32 + 16) * ALD + kt, ALD);
            #pragma unroll
            for (int j = 0; j < 4; j++) {
                wmma::fragment<wmma::matrix_b, 16, 16, 16, __half, wmma::col_major> bf;
                wmma::load_matrix_sync(bf, Bs + (wn * 64 + j * 16) * ALD + kt, ALD);
                wmma::mma_sync(acc[0][j], af0, bf, acc[0][j]);
                wmma::mma_sync(acc[1][j], af1, bf, acc[1][j]);
            }
        }
        __syncthreads();   // Bs dead -> wbuf may clobber

        float* wbuf = (float*)(sm + GSM_WBUF) + wid * 1088;
        const float sc = (n0 < 256) ? SCALE_ : 1.0f;
        const int row  = lane >> 1;
        const int colh = (lane & 1) * 32;

        #pragma unroll
        for (int i = 0; i < 2; i++) {
            #pragma unroll
            for (int j = 0; j < 4; j++)
                wmma::store_matrix_sync(wbuf + j * 16, acc[i][j], 68, wmma::mem_row_major);
            __syncwarp();

            const float* src = wbuf + row * 68 + colh;
            #pragma unroll
            for (int g = 0; g < 2; g++) {
                float4 u0 = *(const float4*)(src + g * 16);
                float4 u1 = *(const float4*)(src + g * 16 + 4);
                float4 u2 = *(const float4*)(src + g * 16 + 8);
                float4 u3 = *(const float4*)(src + g * 16 + 12);
                u0.x *= sc; u0.y *= sc; u0.z *= sc; u0.w *= sc;
                u1.x *= sc; u1.y *= sc; u1.z *= sc; u1.w *= sc;
                u2.x *= sc; u2.y *= sc; u2.z *= sc; u2.w *= sc;
                u3.x *= sc; u3.y *= sc; u3.z *= sc; u3.w *= sc;
                uint4 o0, o1;
                cvt8(u0, u1, o0);
                cvt8(u2, u3, o1);
                const int gr = m0 + wm * 32 + i * 16 + row;
                const int gc = n0 + wn * 64 + colh + g * 16;
                __half* dst = (n0 < 256) ? (g_qh + (size_t)gr * 256 + gc)
                                         : (g_kh + (size_t)gr * 256 + (gc - 256));
                *(uint4*)(dst)     = o0;
                *(uint4*)(dst + 8) = o1;
            }
            __syncwarp();
        }
    }
}

// ---------------------------------------------------------------------------
// Attention: 2x2 tile. Phase 1: slot-0 via 8x8 union rows (each loaded ONCE,
// dotted with all 4 pixels, static edge masks). Phase 2: slots 1/2 as R10.
// ---------------------------------------------------------------------------
__device__ __forceinline__ int reflect_idx(int idx, int L)
{
    const int period = 2 * (L - 1);
    int m = idx % period;
    if (m < 0) m += period;
    return (m > L - 1) ? (period - m) : m;
}

__device__ __forceinline__ float dot8(const uint4& kv, const __half2 q0,
                                      const __half2 q1, const __half2 q2,
                                      const __half2 q3)
{
    __half2 a = __hmul2(*(const __half2*)&kv.x, q0);
    a = __hfma2(*(const __half2*)&kv.y, q1, a);
    a = __hfma2(*(const __half2*)&kv.z, q2, a);
    a = __hfma2(*(const __half2*)&kv.w, q3, a);
    return __half2float(__hadd(__low2half(a), __high2half(a)));
}

__global__ void __launch_bounds__(256) attn_kernel(
    const float* __restrict__ flows, float* __restrict__ out)
{
    const int bid = blockIdx.x;          // 8192 tiles
    const int t   = bid >> 10;
    const int th  = (bid >> 5) & 31;
    const int tw  = bid & 31;
    const int h0  = th * 2;
    const int w0  = tw * 2;

    __shared__ int   off_s[4][NS_ + 8];
    __shared__ int   roff_s[64];
    __shared__ float fl_s[4][NS_ * 3];
    __shared__ float attn_s[4][HEADS_ * NS_];
    __shared__ int   s_fl[4][4];

    const int tid  = threadIdx.x;
    const int warp = tid >> 5;
    const int lane = tid & 31;

    if (tid < 16) {
        const int p   = tid >> 2;
        const int idx = tid & 3;
        const int hwp = (h0 + (p >> 1)) * 64 + w0 + (p & 1);
        const int p_  = idx >> 1, c_ = idx & 1;
        s_fl[p][idx] = (int)rintf(flows[(size_t)((t * 2 + p_) * 2 + c_) * 4096 + hwp]);
    }
    if (tid >= 224 && tid < 256) {             // zero the prefetch pad
        const int p = (tid - 224) >> 3;
        off_s[p][NS_ + ((tid - 224) & 7)] = 0;
    }
    // slot-0 union rows: 8x8 (iu, iv), pixel-independent
    if (tid >= 160 && tid < 224) {
        const int r  = tid - 160;
        const int iu = r >> 3, iv = r & 7;
        roff_s[r] = (t << 12) + reflect_idx(h0 - 3 + iu, H_) * 64
                              + reflect_idx(w0 - 3 + iv, W_);
    }
    __syncthreads();

    for (int e = tid; e < 4 * NS_; e += 256) {
        const int p  = e / NS_;
        const int s  = e - p * NS_;
        const int hp = h0 + (p >> 1);
        const int wp = w0 + (p & 1);
        const int slot = (s >= 49) + (s >= 98);
        const int r = s - slot * 49;
        const int a = r / 7;
        const int b = r - a * 7;
        int di = 0, dj = 0, tp = t;
        if (slot == 1) { tp = (t + 1 < T_) ? t + 1 : t - 2; di = s_fl[p][0]; dj = s_fl[p][1]; }
        if (slot == 2) { tp = (t - 1 >= 0) ? t - 1 : t + 2; di = s_fl[p][2]; dj = s_fl[p][3]; }
        const int li = reflect_idx(hp + di + a - 3, H_);
        const int lj = reflect_idx(wp + dj + b - 3, W_);
        off_s[p][s] = (tp << 12) + li * 64 + lj;
        fl_s[p][s * 3 + 0] = (float)(tp - t);
        fl_s[p][s * 3 + 1] = (float)(li - hp);
        fl_s[p][s * 3 + 2] = (float)(lj - wp);
    }
    __syncthreads();

    const __half* kb = g_kh + lane * 8;
    const int head = lane >> 2;
    const bool wr = (lane & 3) == 0;

    // ================= phase 1: slot-0 union (64 rows, warp = iu) ==========
    {
        __half2 q4[4][4];
        #pragma unroll
        for (int p = 0; p < 4; p++) {
            const int pixp = (t << 12) + (h0 + (p >> 1)) * 64 + w0 + (p & 1);
            const uint4 v = *(const uint4*)(g_qh + (size_t)pixp * 256 + lane * 8);
            q4[p][0] = *(const __half2*)&v.x;
            q4[p][1] = *(const __half2*)&v.y;
            q4[p][2] = *(const __half2*)&v.z;
            q4[p][3] = *(const __half2*)&v.w;
        }

        const int iu = warp;
        uint4 kv = *(const uint4*)(kb + ((size_t)roff_s[iu * 8] << 8));
        #pragma unroll
        for (int iv = 0; iv < 8; iv++) {
            const int nxt = (iv < 7) ? iv + 1 : 7;
            uint4 nv = *(const uint4*)(kb + ((size_t)roff_s[iu * 8 + nxt] << 8));

            float v0 = dot8(kv, q4[0][0], q4[0][1], q4[0][2], q4[0][3]);
            float v1 = dot8(kv, q4[1][0], q4[1][1], q4[1][2], q4[1][3]);
            float v2 = dot8(kv, q4[2][0], q4[2][1], q4[2][2], q4[2][3]);
            float v3 = dot8(kv, q4[3][0], q4[3][1], q4[3][2], q4[3][3]);
            v0 += __shfl_xor_sync(0xffffffffu, v0, 1);
            v1 += __shfl_xor_sync(0xffffffffu, v1, 1);
            v2 += __shfl_xor_sync(0xffffffffu, v2, 1);
            v3 += __shfl_xor_sync(0xffffffffu, v3, 1);
            v0 += __shfl_xor_sync(0xffffffffu, v0, 2);
            v1 += __shfl_xor_sync(0xffffffffu, v1, 2);
            v2 += __shfl_xor_sync(0xffffffffu, v2, 2);
            v3 += __shfl_xor_sync(0xffffffffu, v3, 2);
            if (wr) {
                if (iu < 7  && iv < 7)  attn_s[0][head * NS_ + iu * 7 + iv]           = v0;
                if (iu < 7  && iv >= 1) attn_s[1][head * NS_ + iu * 7 + iv - 1]       = v1;
                if (iu >= 1 && iv < 7)  attn_s[2][head * NS_ + (iu - 1) * 7 + iv]     = v2;
                if (iu >= 1 && iv >= 1) attn_s[3][head * NS_ + (iu - 1) * 7 + iv - 1] = v3;
            }
            kv = nv;
        }
    }

    // ================= phase 2: slots 1/2 (keys 49..146), warp owns 2 pixels
    {
        const int p0    = (warp >> 2) * 2;
        const int sbase = 49 + (warp & 3);

        __half2 q[2][4];
        #pragma unroll
        for (int i = 0; i < 2; i++) {
            const int p = p0 + i;
            const int pixp = (t << 12) + (h0 + (p >> 1)) * 64 + w0 + (p & 1);
            const uint4 v = *(const uint4*)(g_qh + (size_t)pixp * 256 + lane * 8);
            q[i][0] = *(const __half2*)&v.x;
            q[i][1] = *(const __half2*)&v.y;
            q[i][2] = *(const __half2*)&v.z;
            q[i][3] = *(const __half2*)&v.w;
        }

        uint4 kv[2];
        kv[0] = *(const uint4*)(kb + ((size_t)off_s[p0][sbase]     << 8));
        kv[1] = *(const uint4*)(kb + ((size_t)off_s[p0 + 1][sbase] << 8));

        for (int s = sbase; s < NS_; s += 4) {
            const int sn = (s + 4 < NS_) ? s + 4 : NS_;
            uint4 nv0 = *(const uint4*)(kb + ((size_t)off_s[p0][sn]     << 8));
            uint4 nv1 = *(const uint4*)(kb + ((size_t)off_s[p0 + 1][sn] << 8));

            float v0 = dot8(kv[0], q[0][0], q[0][1], q[0][2], q[0][3]);
            float v1 = dot8(kv[1], q[1][0], q[1][1], q[1][2], q[1][3]);
            v0 += __shfl_xor_sync(0xffffffffu, v0, 1);
            v1 += __shfl_xor_sync(0xffffffffu, v1, 1);
            v0 += __shfl_xor_sync(0xffffffffu, v0, 2);
            v1 += __shfl_xor_sync(0xffffffffu, v1, 2);
            if (wr) {
                attn_s[p0][head * NS_ + s]     = v0;
                attn_s[p0 + 1][head * NS_ + s] = v1;
            }
            kv[0] = nv0;
            kv[1] = nv1;
        }
    }
    __syncthreads();

    // attn stores: (1, HEADS, T, H, W, 147)
    #pragma unroll
    for (int p = 0; p < 4; p++) {
        const int hwp = (h0 + (p >> 1)) * 64 + w0 + (p & 1);
        #pragma unroll
        for (int hd = 0; hd < HEADS_; hd++) {
            if (tid < NS_)
                out[(size_t)((hd * T_ + t) * 4096 + hwp) * NS_ + tid] =
                    attn_s[p][hd * NS_ + tid];
        }
    }

    // flows_k stores: (1, HEADS, T, H, W, 147, 3)
    const size_t FBASE = (size_t)HEADS_ * T_ * 4096 * NS_;  // 38,535,168
    #pragma unroll
    for (int p = 0; p < 4; p++) {
        const int hwp = (h0 + (p >> 1)) * 64 + w0 + (p & 1);
        #pragma unroll
        for (int hd = 0; hd < HEADS_; hd++) {
            const size_t base = FBASE + (size_t)((hd * T_ + t) * 4096 + hwp) * (NS_ * 3);
            out[base + tid] = fl_s[p][tid];
            if (tid + 256 < NS_ * 3)
                out[base + tid + 256] = fl_s[p][tid + 256];
        }
    }
}

// ---------------------------------------------------------------------------
extern "C" void kernel_launch(void* const* d_in, const int* in_sizes, int n_in,
                              void* d_out, int out_size)
{
    const float* x     = (const float*)d_in[0];   // (8,64,64,256)
    const float* flows = (const float*)d_in[1];   // (1,8,2,2,64,64)
    const float* wqk   = (const float*)d_in[2];   // (512,256)
    float* out = (float*)d_out;

    cudaFuncSetAttribute(gemm_qk_kernel,
                         cudaFuncAttributeMaxDynamicSharedMemorySize, GSM_TOTAL);

    cvtw_kernel<<<64, 256>>>(wqk);
    gemm_qk_kernel<<<M_ / 128, 256, GSM_TOTAL>>>(x);
    attn_kernel<<<NPIX / 4, 256>>>(flows, out);
}

// round 16
// speedup vs baseline: 1.5743x; 1.0344x over previous
#include <cuda_runtime.h>
#include <cuda_fp16.h>
#include <cstdint>
#include <mma.h>

using namespace nvcuda;

#define T_      8
#define H_      64
#define W_      64
#define C_      256
#define HEADS_  8
#define WS_     7
#define NPIX    (T_ * H_ * W_)          // 32768
#define M_      NPIX
#define N_      512
#define K_      256
#define NS_     (3 * WS_ * WS_)         // 147
#define SCALE_  0.17677669529663687f    // 32^-0.5

// fp16 inputs + projected q (pre-scaled) / k
__device__ __align__(16) __half g_xh[(size_t)NPIX * 256];
__device__ __align__(16) __half g_wh[(size_t)512 * 256];
__device__ __align__(16) __half g_qh[(size_t)NPIX * 256];
__device__ __align__(16) __half g_kh[(size_t)NPIX * 256];

__device__ __forceinline__ void cvt8(const float4 u, const float4 v, uint4& o)
{
    __half2 p0 = __floats2half2_rn(u.x, u.y);
    __half2 p1 = __floats2half2_rn(u.z, u.w);
    __half2 p2 = __floats2half2_rn(v.x, v.y);
    __half2 p3 = __floats2half2_rn(v.z, v.w);
    o.x = *(unsigned*)&p0; o.y = *(unsigned*)&p1;
    o.z = *(unsigned*)&p2; o.w = *(unsigned*)&p3;
}

// ---------------------------------------------------------------------------
// convert x and W_qk to fp16 (one kernel)
// ---------------------------------------------------------------------------
#define XN_ (NPIX * 256)          // 8388608
#define WN_ (512 * 256)           // 131072

__global__ void __launch_bounds__(256) cvt_kernel(
    const float* __restrict__ x, const float* __restrict__ wqk)
{
    const int idx = blockIdx.x * 256 + threadIdx.x;
    const long base = (long)idx * 8;
    const float* src;
    __half* dst;
    if (base < XN_) { src = x + base;           dst = g_xh + base; }
    else            { src = wqk + (base - XN_); dst = g_wh + (base - XN_); }
    uint4 o;
    cvt8(*(const float4*)src, *(const float4*)(src + 4), o);
    *(uint4*)dst = o;
}

// ---------------------------------------------------------------------------
// GEMM: 128x64 tile, K chunks of 64, cp.async double-buffered, fp16 in/out.
// Grid (256, 8); 55.3KB smem -> 4 blocks/SM.
// ---------------------------------------------------------------------------
#define GPITCH 72                   // halfs pitch for A and B tiles
#define ABUF_H (128 * GPITCH)       // 9216 halfs
#define BBUF_H (64 * GPITCH)        // 4608 halfs
#define GSM_TOTAL ((ABUF_H + BBUF_H) * 2 * 2)   // 55296 bytes

__device__ __forceinline__ void cp16(void* smem_dst, const void* gmem_src)
{
    uint32_t d = (uint32_t)__cvta_generic_to_shared(smem_dst);
    asm volatile("cp.async.cg.shared.global [%0], [%1], 16;\n"
                 :: "r"(d), "l"(gmem_src) : "memory");
}

__global__ void __launch_bounds__(256) gemm_qk_kernel()
{
    extern __shared__ __align__(16) char sm[];
    __half* bufh = (__half*)sm;
    // layout: [A0 | B0 | A1 | B1]
    __half* As[2] = { bufh,                    bufh + ABUF_H + BBUF_H };
    __half* Bs[2] = { bufh + ABUF_H,           bufh + 2 * ABUF_H + BBUF_H };

    const int m0   = blockIdx.x * 128;
    const int n0   = blockIdx.y * 64;
    const int tid  = threadIdx.x;
    const int wid  = tid >> 5;
    const int lane = tid & 31;
    const int wm   = wid & 3;    // 4 M-groups of 32 rows
    const int wn   = wid >> 2;   // 2 N-groups of 32 cols

    // ---- staging helper (A: 128x64 halfs, B: 64x64 halfs) ----
    auto stage = [&](int kt, int b) {
        #pragma unroll
        for (int i = 0; i < 4; i++) {
            const int e   = i * 256 + tid;   // 0..1023
            const int row = e >> 3;          // 0..127
            const int c8  = (e & 7) * 8;     // halfs
            cp16(As[b] + row * GPITCH + c8,
                 g_xh + (size_t)(m0 + row) * 256 + kt + c8);
        }
        #pragma unroll
        for (int i = 0; i < 2; i++) {
            const int e   = i * 256 + tid;   // 0..511
            const int row = e >> 3;          // 0..63
            const int c8  = (e & 7) * 8;
            cp16(Bs[b] + row * GPITCH + c8,
                 g_wh + (size_t)(n0 + row) * 256 + kt + c8);
        }
        asm volatile("cp.async.commit_group;\n" ::: "memory");
    };

    wmma::fragment<wmma::accumulator, 16, 16, 16, float> acc[2][2];
    #pragma unroll
    for (int i = 0; i < 2; i++)
        #pragma unroll
        for (int j = 0; j < 2; j++)
            wmma::fill_fragment(acc[i][j], 0.0f);

    stage(0, 0);

    #pragma unroll
    for (int c = 0; c < 4; c++) {
        const int b = c & 1;
        if (c < 3) stage((c + 1) * 64, b ^ 1);
        if (c < 3) asm volatile("cp.async.wait_group 1;\n" ::: "memory");
        else       asm volatile("cp.async.wait_group 0;\n" ::: "memory");
        __syncthreads();   // chunk c visible to all warps

        #pragma unroll
        for (int kk = 0; kk < 64; kk += 16) {
            wmma::fragment<wmma::matrix_a, 16, 16, 16, __half, wmma::row_major> af0, af1;
            wmma::fragment<wmma::matrix_b, 16, 16, 16, __half, wmma::col_major> bf0, bf1;
            wmma::load_matrix_sync(af0, As[b] + (wm * 32)      * GPITCH + kk, GPITCH);
            wmma::load_matrix_sync(af1, As[b] + (wm * 32 + 16) * GPITCH + kk, GPITCH);
            wmma::load_matrix_sync(bf0, Bs[b] + (wn * 32)      * GPITCH + kk, GPITCH);
            wmma::load_matrix_sync(bf1, Bs[b] + (wn * 32 + 16) * GPITCH + kk, GPITCH);
            wmma::mma_sync(acc[0][0], af0, bf0, acc[0][0]);
            wmma::mma_sync(acc[0][1], af0, bf1, acc[0][1]);
            wmma::mma_sync(acc[1][0], af1, bf0, acc[1][0]);
            wmma::mma_sync(acc[1][1], af1, bf1, acc[1][1]);
        }
        __syncthreads();   // all warps done with buffer b before restage (c+2)
    }

    // ---- epilogue: restage via smem (aliases buffers), fp16 out ----
    float* wbuf = (float*)sm + wid * 1152;   // 32 rows x pitch 36
    wmma::store_matrix_sync(wbuf,                acc[0][0], 36, wmma::mem_row_major);
    wmma::store_matrix_sync(wbuf + 16,           acc[0][1], 36, wmma::mem_row_major);
    wmma::store_matrix_sync(wbuf + 16 * 36,      acc[1][0], 36, wmma::mem_row_major);
    wmma::store_matrix_sync(wbuf + 16 * 36 + 16, acc[1][1], 36, wmma::mem_row_major);
    __syncwarp();

    const float sc = (n0 < 256) ? SCALE_ : 1.0f;
    const float* src = wbuf + lane * 36;
    uint4 o[4];
    #pragma unroll
    for (int g = 0; g < 4; g++) {
        float4 u = *(const float4*)(src + g * 8);
        float4 v = *(const float4*)(src + g * 8 + 4);
        u.x *= sc; u.y *= sc; u.z *= sc; u.w *= sc;
        v.x *= sc; v.y *= sc; v.z *= sc; v.w *= sc;
        cvt8(u, v, o[g]);
    }
    const int gr = m0 + wm * 32 + lane;
    const int gc = n0 + wn * 32;
    __half* dst = (n0 < 256) ? (g_qh + (size_t)gr * 256 + gc)
                             : (g_kh + (size_t)gr * 256 + (gc - 256));
    *(uint4*)(dst)      = o[0];
    *(uint4*)(dst + 8)  = o[1];
    *(uint4*)(dst + 16) = o[2];
    *(uint4*)(dst + 24) = o[3];
}

// ---------------------------------------------------------------------------
// Attention (R15 proven): 2x2 tile; phase 1 slot-0 via 8x8 union rows,
// phase 2 slots 1/2 warp-owns-2-pixels with prefetch.
// ---------------------------------------------------------------------------
__device__ __forceinline__ int reflect_idx(int idx, int L)
{
    const int period = 2 * (L - 1);
    int m = idx % period;
    if (m < 0) m += period;
    return (m > L - 1) ? (period - m) : m;
}

__device__ __forceinline__ float dot8(const uint4& kv, const __half2 q0,
                                      const __half2 q1, const __half2 q2,
                                      const __half2 q3)
{
    __half2 a = __hmul2(*(const __half2*)&kv.x, q0);
    a = __hfma2(*(const __half2*)&kv.y, q1, a);
    a = __hfma2(*(const __half2*)&kv.z, q2, a);
    a = __hfma2(*(const __half2*)&kv.w, q3, a);
    return __half2float(__hadd(__low2half(a), __high2half(a)));
}

__global__ void __launch_bounds__(256) attn_kernel(
    const float* __restrict__ flows, float* __restrict__ out)
{
    const int bid = blockIdx.x;          // 8192 tiles
    const int t   = bid >> 10;
    const int th  = (bid >> 5) & 31;
    const int tw  = bid & 31;
    const int h0  = th * 2;
    const int w0  = tw * 2;

    __shared__ int   off_s[4][NS_ + 8];
    __shared__ int   roff_s[64];
    __shared__ float fl_s[4][NS_ * 3];
    __shared__ float attn_s[4][HEADS_ * NS_];
    __shared__ int   s_fl[4][4];

    const int tid  = threadIdx.x;
    const int warp = tid >> 5;
    const int lane = tid & 31;

    if (tid < 16) {
        const int p   = tid >> 2;
        const int idx = tid & 3;
        const int hwp = (h0 + (p >> 1)) * 64 + w0 + (p & 1);
        const int p_  = idx >> 1, c_ = idx & 1;
        s_fl[p][idx] = (int)rintf(flows[(size_t)((t * 2 + p_) * 2 + c_) * 4096 + hwp]);
    }
    if (tid >= 224 && tid < 256) {             // zero the prefetch pad
        const int p = (tid - 224) >> 3;
        off_s[p][NS_ + ((tid - 224) & 7)] = 0;
    }
    // slot-0 union rows: 8x8 (iu, iv), pixel-independent
    if (tid >= 160 && tid < 224) {
        const int r  = tid - 160;
        const int iu = r >> 3, iv = r & 7;
        roff_s[r] = (t << 12) + reflect_idx(h0 - 3 + iu, H_) * 64
                              + reflect_idx(w0 - 3 + iv, W_);
    }
    __syncthreads();

    for (int e = tid; e < 4 * NS_; e += 256) {
        const int p  = e / NS_;
        const int s  = e - p * NS_;
        const int hp = h0 + (p >> 1);
        const int wp = w0 + (p & 1);
        const int slot = (s >= 49) + (s >= 98);
        const int r = s - slot * 49;
        const int a = r / 7;
        const int b = r - a * 7;
        int di = 0, dj = 0, tp = t;
        if (slot == 1) { tp = (t + 1 < T_) ? t + 1 : t - 2; di = s_fl[p][0]; dj = s_fl[p][1]; }
        if (slot == 2) { tp = (t - 1 >= 0) ? t - 1 : t + 2; di = s_fl[p][2]; dj = s_fl[p][3]; }
        const int li = reflect_idx(hp + di + a - 3, H_);
        const int lj = reflect_idx(wp + dj + b - 3, W_);
        off_s[p][s] = (tp << 12) + li * 64 + lj;
        fl_s[p][s * 3 + 0] = (float)(tp - t);
        fl_s[p][s * 3 + 1] = (float)(li - hp);
        fl_s[p][s * 3 + 2] = (float)(lj - wp);
    }
    __syncthreads();

    const __half* kb = g_kh + lane * 8;
    const int head = lane >> 2;
    const bool wr = (lane & 3) == 0;

    // ================= phase 1: slot-0 union (64 rows, warp = iu) ==========
    {
        __half2 q4[4][4];
        #pragma unroll
        for (int p = 0; p < 4; p++) {
            const int pixp = (t << 12) + (h0 + (p >> 1)) * 64 + w0 + (p & 1);
            const uint4 v = *(const uint4*)(g_qh + (size_t)pixp * 256 + lane * 8);
            q4[p][0] = *(const __half2*)&v.x;
            q4[p][1] = *(const __half2*)&v.y;
            q4[p][2] = *(const __half2*)&v.z;
            q4[p][3] = *(const __half2*)&v.w;
        }

        const int iu = warp;
        uint4 kv = *(const uint4*)(kb + ((size_t)roff_s[iu * 8] << 8));
        #pragma unroll
        for (int iv = 0; iv < 8; iv++) {
            const int nxt = (iv < 7) ? iv + 1 : 7;
            uint4 nv = *(const uint4*)(kb + ((size_t)roff_s[iu * 8 + nxt] << 8));

            float v0 = dot8(kv, q4[0][0], q4[0][1], q4[0][2], q4[0][3]);
            float v1 = dot8(kv, q4[1][0], q4[1][1], q4[1][2], q4[1][3]);
            float v2 = dot8(kv, q4[2][0], q4[2][1], q4[2][2], q4[2][3]);
            float v3 = dot8(kv, q4[3][0], q4[3][1], q4[3][2], q4[3][3]);
            v0 += __shfl_xor_sync(0xffffffffu, v0, 1);
            v1 += __shfl_xor_sync(0xffffffffu, v1, 1);
            v2 += __shfl_xor_sync(0xffffffffu, v2, 1);
            v3 += __shfl_xor_sync(0xffffffffu, v3, 1);
            v0 += __shfl_xor_sync(0xffffffffu, v0, 2);
            v1 += __shfl_xor_sync(0xffffffffu, v1, 2);
            v2 += __shfl_xor_sync(0xffffffffu, v2, 2);
            v3 += __shfl_xor_sync(0xffffffffu, v3, 2);
            if (wr) {
                if (iu < 7  && iv < 7)  attn_s[0][head * NS_ + iu * 7 + iv]           = v0;
                if (iu < 7  && iv >= 1) attn_s[1][head * NS_ + iu * 7 + iv - 1]       = v1;
                if (iu >= 1 && iv < 7)  attn_s[2][head * NS_ + (iu - 1) * 7 + iv]     = v2;
                if (iu >= 1 && iv >= 1) attn_s[3][head * NS_ + (iu - 1) * 7 + iv - 1] = v3;
            }
            kv = nv;
        }
    }

    // ================= phase 2: slots 1/2 (keys 49..146), warp owns 2 pixels
    {
        const int p0    = (warp >> 2) * 2;
        const int sbase = 49 + (warp & 3);

        __half2 q[2][4];
        #pragma unroll
        for (int i = 0; i < 2; i++) {
            const int p = p0 + i;
            const int pixp = (t << 12) + (h0 + (p >> 1)) * 64 + w0 + (p & 1);
            const uint4 v = *(const uint4*)(g_qh + (size_t)pixp * 256 + lane * 8);
            q[i][0] = *(const __half2*)&v.x;
            q[i][1] = *(const __half2*)&v.y;
            q[i][2] = *(const __half2*)&v.z;
            q[i][3] = *(const __half2*)&v.w;
        }

        uint4 kv[2];
        kv[0] = *(const uint4*)(kb + ((size_t)off_s[p0][sbase]     << 8));
        kv[1] = *(const uint4*)(kb + ((size_t)off_s[p0 + 1][sbase] << 8));

        for (int s = sbase; s < NS_; s += 4) {
            const int sn = (s + 4 < NS_) ? s + 4 : NS_;
            uint4 nv0 = *(const uint4*)(kb + ((size_t)off_s[p0][sn]     << 8));
            uint4 nv1 = *(const uint4*)(kb + ((size_t)off_s[p0 + 1][sn] << 8));

            float v0 = dot8(kv[0], q[0][0], q[0][1], q[0][2], q[0][3]);
            float v1 = dot8(kv[1], q[1][0], q[1][1], q[1][2], q[1][3]);
            v0 += __shfl_xor_sync(0xffffffffu, v0, 1);
            v1 += __shfl_xor_sync(0xffffffffu, v1, 1);
            v0 += __shfl_xor_sync(0xffffffffu, v0, 2);
            v1 += __shfl_xor_sync(0xffffffffu, v1, 2);
            if (wr) {
                attn_s[p0][head * NS_ + s]     = v0;
                attn_s[p0 + 1][head * NS_ + s] = v1;
            }
            kv[0] = nv0;
            kv[1] = nv1;
        }
    }
    __syncthreads();

    // attn stores: (1, HEADS, T, H, W, 147)
    #pragma unroll
    for (int p = 0; p < 4; p++) {
        const int hwp = (h0 + (p >> 1)) * 64 + w0 + (p & 1);
        #pragma unroll
        for (int hd = 0; hd < HEADS_; hd++) {
            if (tid < NS_)
                out[(size_t)((hd * T_ + t) * 4096 + hwp) * NS_ + tid] =
                    attn_s[p][hd * NS_ + tid];
        }
    }

    // flows_k stores: (1, HEADS, T, H, W, 147, 3)
    const size_t FBASE = (size_t)HEADS_ * T_ * 4096 * NS_;  // 38,535,168
    #pragma unroll
    for (int p = 0; p < 4; p++) {
        const int hwp = (h0 + (p >> 1)) * 64 + w0 + (p & 1);
        #pragma unroll
        for (int hd = 0; hd < HEADS_; hd++) {
            const size_t base = FBASE + (size_t)((hd * T_ + t) * 4096 + hwp) * (NS_ * 3);
            out[base + tid] = fl_s[p][tid];
            if (tid + 256 < NS_ * 3)
                out[base + tid + 256] = fl_s[p][tid + 256];
        }
    }
}

// ---------------------------------------------------------------------------
extern "C" void kernel_launch(void* const* d_in, const int* in_sizes, int n_in,
                              void* d_out, int out_size)
{
    const float* x     = (const float*)d_in[0];   // (8,64,64,256)
    const float* flows = (const float*)d_in[1];   // (1,8,2,2,64,64)
    const float* wqk   = (const float*)d_in[2];   // (512,256)
    float* out = (float*)d_out;

    cudaFuncSetAttribute(gemm_qk_kernel,
                         cudaFuncAttributeMaxDynamicSharedMemorySize, GSM_TOTAL);

    cvt_kernel<<<(XN_ + WN_) / 8 / 256, 256>>>(x, wqk);
    dim3 gg(M_ / 128, N_ / 64);
    gemm_qk_kernel<<<gg, 256, GSM_TOTAL>>>();
    attn_kernel<<<NPIX / 4, 256>>>(flows, out);
}